// round 3
// baseline (speedup 1.0000x reference)
#include <cuda_runtime.h>

#define NN 50000
#define NE 800000
#define DD 96

// ---------------- scratch (device globals; no allocation allowed) ----------
__device__ int   g_cnt [NN];
__device__ int   g_off [NN + 1];
__device__ int   g_fill[NN];
__device__ float g_dinv[NN];
__device__ int   g_src [NE];
__device__ float g_wn  [NE];
__device__ __align__(16) float g_hA[(size_t)NN * DD];
__device__ __align__(16) float g_hB[(size_t)NN * DD];

// ---------------- graph preprocessing --------------------------------------
__global__ void k_zero()
{
    int i = blockIdx.x * blockDim.x + threadIdx.x;
    if (i < NN) g_cnt[i] = 0;
}

__global__ void k_hist(const int* __restrict__ dst)
{
    int e = blockIdx.x * blockDim.x + threadIdx.x;
    if (e < NE) atomicAdd(&g_cnt[dst[e]], 1);
}

// Single-block exclusive scan of g_cnt -> g_off/g_fill, plus dinv = rsqrt(cnt+1).
__global__ void k_scan()
{
    __shared__ int wsum[32];
    __shared__ int s_carry;
    int tid = threadIdx.x, lane = tid & 31, wid = tid >> 5;
    if (tid == 0) s_carry = 0;
    __syncthreads();

    for (int base = 0; base < NN; base += 1024) {
        int i = base + tid;
        int v = (i < NN) ? g_cnt[i] : 0;
        int inc = v;
        #pragma unroll
        for (int d = 1; d < 32; d <<= 1) {
            int t = __shfl_up_sync(0xffffffffu, inc, d);
            if (lane >= d) inc += t;
        }
        if (lane == 31) wsum[wid] = inc;
        __syncthreads();
        if (wid == 0) {
            int w = wsum[lane];
            int wi = w;
            #pragma unroll
            for (int d = 1; d < 32; d <<= 1) {
                int t = __shfl_up_sync(0xffffffffu, wi, d);
                if (lane >= d) wi += t;
            }
            wsum[lane] = wi - w;   // exclusive prefix of warp sums
        }
        __syncthreads();
        int excl = s_carry + wsum[wid] + inc - v;
        if (i < NN) {
            g_off[i]  = excl;
            g_fill[i] = excl;
            g_dinv[i] = rsqrtf((float)(v + 1));
        }
        __syncthreads();
        if (tid == 1023) s_carry = excl + v;   // chunk-inclusive total
        __syncthreads();
    }
    if (tid == 0) g_off[NN] = s_carry;
}

__global__ void k_fill(const int* __restrict__ src,
                       const int* __restrict__ dst)
{
    int e = blockIdx.x * blockDim.x + threadIdx.x;
    if (e < NE) {
        int s = src[e];
        int d = dst[e];
        int p = atomicAdd(&g_fill[d], 1);
        g_src[p] = s;
        g_wn[p]  = g_dinv[s] * g_dinv[d];
    }
}

// ---------------- GEMM: g_hA = Xin @ W  (Xin: [NN,96], W: [96,96]) ---------
// Xin = external x when Xext != nullptr (layer 0), else g_hB.
// BM=64, BN=96, full-K in smem. 384 threads: each computes a 4x4 tile.
__global__ __launch_bounds__(384) void k_gemm(const float* __restrict__ Xext,
                                              const float* __restrict__ W)
{
    __shared__ float Ws[96 * 96];
    __shared__ float Xs[64 * 96];
    int tid = threadIdx.x;

    const float* X = Xext ? Xext : g_hB;

    const float4* W4  = (const float4*)W;
    float4*       Ws4 = (float4*)Ws;
    #pragma unroll
    for (int i = 0; i < 6; i++) Ws4[tid + i * 384] = W4[tid + i * 384];

    int row0 = blockIdx.x * 64;
    float4* Xs4 = (float4*)Xs;
    #pragma unroll
    for (int i = 0; i < 4; i++) {
        int idx = tid + i * 384;        // 0..1535
        int m = idx / 24, q = idx % 24;
        int row = row0 + m;
        float4 v = make_float4(0.f, 0.f, 0.f, 0.f);
        if (row < NN) v = ((const float4*)(X + (size_t)row * 96))[q];
        Xs4[m * 24 + q] = v;
    }
    __syncthreads();

    int tn = tid % 24;      // 4-col group
    int tm = tid / 24;      // 4-row group
    float acc[4][4];
    #pragma unroll
    for (int i = 0; i < 4; i++)
        #pragma unroll
        for (int j = 0; j < 4; j++) acc[i][j] = 0.f;

    #pragma unroll 4
    for (int k = 0; k < 96; k++) {
        float a0 = Xs[(tm * 4 + 0) * 96 + k];
        float a1 = Xs[(tm * 4 + 1) * 96 + k];
        float a2 = Xs[(tm * 4 + 2) * 96 + k];
        float a3 = Xs[(tm * 4 + 3) * 96 + k];
        float4 b = *(const float4*)&Ws[k * 96 + tn * 4];
        acc[0][0] += a0 * b.x; acc[0][1] += a0 * b.y; acc[0][2] += a0 * b.z; acc[0][3] += a0 * b.w;
        acc[1][0] += a1 * b.x; acc[1][1] += a1 * b.y; acc[1][2] += a1 * b.z; acc[1][3] += a1 * b.w;
        acc[2][0] += a2 * b.x; acc[2][1] += a2 * b.y; acc[2][2] += a2 * b.z; acc[2][3] += a2 * b.w;
        acc[3][0] += a3 * b.x; acc[3][1] += a3 * b.y; acc[3][2] += a3 * b.z; acc[3][3] += a3 * b.w;
    }

    #pragma unroll
    for (int i = 0; i < 4; i++) {
        int row = row0 + tm * 4 + i;
        if (row < NN)
            *(float4*)&g_hA[(size_t)row * 96 + tn * 4] =
                make_float4(acc[i][0], acc[i][1], acc[i][2], acc[i][3]);
    }
}

// ---------------- aggregation: g_hB = relu(A_hat @ g_hA + b) ---------------
// One warp per node. Lanes cover the 96 features (3 per lane, coalesced).
__global__ __launch_bounds__(256) void k_agg(const float* __restrict__ bias)
{
    int node = blockIdx.x * 8 + threadIdx.y;
    if (node >= NN) return;
    int lane = threadIdx.x;

    const float* H = g_hA;

    float di = g_dinv[node];
    float wself = di * di;
    const float* hr = H + (size_t)node * 96;
    float a0 = wself * hr[lane];
    float a1 = wself * hr[lane + 32];
    float a2 = wself * hr[lane + 64];

    int j  = g_off[node];
    int e1 = g_off[node + 1];
    for (; j < e1; j++) {
        int   s = g_src[j];
        float w = g_wn[j];
        const float* hs = H + (size_t)s * 96;
        a0 += w * hs[lane];
        a1 += w * hs[lane + 32];
        a2 += w * hs[lane + 64];
    }
    a0 += bias[lane];
    a1 += bias[lane + 32];
    a2 += bias[lane + 64];
    size_t o = (size_t)node * 96 + lane;
    g_hB[o]      = fmaxf(a0, 0.f);
    g_hB[o + 32] = fmaxf(a1, 0.f);
    g_hB[o + 64] = fmaxf(a2, 0.f);
}

// ---------------- final FC: out = g_hB @ Wfc + bfc  (96 -> 4) --------------
__global__ __launch_bounds__(256) void k_fc(const float* __restrict__ Wfc,
                                            const float* __restrict__ bfc,
                                            float* __restrict__ Out)
{
    __shared__ float sW[96 * 4];
    __shared__ float sb[4];
    int tid = threadIdx.x;
    for (int i = tid; i < 96 * 4; i += 256) sW[i] = Wfc[i];
    if (tid < 4) sb[tid] = bfc[tid];
    __syncthreads();

    int i = blockIdx.x * 256 + tid;
    if (i >= NN) return;
    const float4* h4 = (const float4*)(g_hB + (size_t)i * 96);
    float acc0 = sb[0], acc1 = sb[1], acc2 = sb[2], acc3 = sb[3];
    #pragma unroll
    for (int kq = 0; kq < 24; kq++) {
        float4 x = h4[kq];
        int k = kq * 4;
        acc0 += x.x * sW[(k + 0) * 4 + 0]; acc1 += x.x * sW[(k + 0) * 4 + 1];
        acc2 += x.x * sW[(k + 0) * 4 + 2]; acc3 += x.x * sW[(k + 0) * 4 + 3];
        acc0 += x.y * sW[(k + 1) * 4 + 0]; acc1 += x.y * sW[(k + 1) * 4 + 1];
        acc2 += x.y * sW[(k + 1) * 4 + 2]; acc3 += x.y * sW[(k + 1) * 4 + 3];
        acc0 += x.z * sW[(k + 2) * 4 + 0]; acc1 += x.z * sW[(k + 2) * 4 + 1];
        acc2 += x.z * sW[(k + 2) * 4 + 2]; acc3 += x.z * sW[(k + 2) * 4 + 3];
        acc0 += x.w * sW[(k + 3) * 4 + 0]; acc1 += x.w * sW[(k + 3) * 4 + 1];
        acc2 += x.w * sW[(k + 3) * 4 + 2]; acc3 += x.w * sW[(k + 3) * 4 + 3];
    }
    *(float4*)&Out[(size_t)i * 4] = make_float4(acc0, acc1, acc2, acc3);
}

// ---------------- launch ----------------------------------------------------
extern "C" void kernel_launch(void* const* d_in, const int* in_sizes, int n_in,
                              void* d_out, int out_size)
{
    const float* x    = (const float*)d_in[0];
    const int*   ei   = (const int*)d_in[1];     // JAX default: int32, [2, NE]
    const float* W0   = (const float*)d_in[2];
    const float* b0   = (const float*)d_in[3];
    const float* W1   = (const float*)d_in[4];
    const float* b1   = (const float*)d_in[5];
    const float* W2   = (const float*)d_in[6];
    const float* b2   = (const float*)d_in[7];
    const float* Wfc  = (const float*)d_in[8];
    const float* bfc  = (const float*)d_in[9];
    float*       out  = (float*)d_out;

    const int* srcE = ei;
    const int* dstE = ei + NE;

    int gb_n = (NN + 255) / 256;
    int gb_e = (NE + 255) / 256;

    // graph preprocessing
    k_zero<<<gb_n, 256>>>();
    k_hist<<<gb_e, 256>>>(dstE);
    k_scan<<<1, 1024>>>();
    k_fill<<<gb_e, 256>>>(srcE, dstE);

    int gemm_blocks = (NN + 63) / 64;
    dim3 agg_block(32, 8);
    int agg_blocks = (NN + 7) / 8;

    // layer 0: gemm(x -> hA), agg(hA -> hB)
    k_gemm<<<gemm_blocks, 384>>>(x, W0);
    k_agg <<<agg_blocks, agg_block>>>(b0);
    // layer 1: gemm(hB -> hA), agg(hA -> hB)
    k_gemm<<<gemm_blocks, 384>>>(nullptr, W1);
    k_agg <<<agg_blocks, agg_block>>>(b1);
    // layer 2
    k_gemm<<<gemm_blocks, 384>>>(nullptr, W2);
    k_agg <<<agg_blocks, agg_block>>>(b2);
    // head
    k_fc<<<gb_n, 256>>>(Wfc, bfc, out);

    (void)in_sizes; (void)n_in; (void)out_size;
}

// round 4
// speedup vs baseline: 1.2789x; 1.2789x over previous
#include <cuda_runtime.h>

#define NN 50000
#define NE 800000
#define DD 96

// ---------------- scratch (device globals; no allocation allowed) ----------
__device__ __align__(16) int   g_cnt [NN];
__device__ __align__(16) int   g_off [NN + 4];
__device__ __align__(16) int   g_fill[NN];
__device__ __align__(16) float g_dinv[NN];
__device__ __align__(16) int2  g_edge[NE];      // .x = src, .y = bits(wn)
__device__ __align__(16) float g_hA[(size_t)NN * DD];
__device__ __align__(16) float g_hB[(size_t)NN * DD];

// ---------------- f32x2 helpers ---------------------------------------------
__device__ __forceinline__ unsigned long long pk2(float x, float y)
{
    unsigned long long r;
    asm("mov.b64 %0, {%1,%2};" : "=l"(r) : "f"(x), "f"(y));
    return r;
}
__device__ __forceinline__ void upk2(unsigned long long v, float& x, float& y)
{
    asm("mov.b64 {%0,%1}, %2;" : "=f"(x), "=f"(y) : "l"(v));
}
__device__ __forceinline__ void ffma2(unsigned long long& d,
                                      unsigned long long a,
                                      unsigned long long b)
{
    asm("fma.rn.f32x2 %0, %1, %2, %0;" : "+l"(d) : "l"(a), "l"(b));
}

// ---------------- graph preprocessing --------------------------------------
__global__ void k_zero()
{
    int i = blockIdx.x * blockDim.x + threadIdx.x;
    if (i < NN) g_cnt[i] = 0;
}

__global__ void k_hist(const int* __restrict__ dst)
{
    int e = blockIdx.x * blockDim.x + threadIdx.x;
    if (e < NE) atomicAdd(&g_cnt[dst[e]], 1);
}

// Single-block exclusive scan (4 elems/thread, int4): g_cnt -> g_off/g_fill,
// plus dinv = rsqrt(cnt+1).  NN/4 = 12500 int4 quads, 13 rounds of 1024.
__global__ void k_scan()
{
    __shared__ int wsum[32];
    __shared__ int s_carry;
    int tid = threadIdx.x, lane = tid & 31, wid = tid >> 5;
    if (tid == 0) s_carry = 0;
    __syncthreads();

    const int NQ = NN / 4;
    for (int base = 0; base < NQ; base += 1024) {
        int i = base + tid;
        int4 v = make_int4(0, 0, 0, 0);
        if (i < NQ) v = ((const int4*)g_cnt)[i];
        int t0 = v.x, t1 = t0 + v.y, t2 = t1 + v.z, t3 = t2 + v.w;

        int inc = t3;
        #pragma unroll
        for (int d = 1; d < 32; d <<= 1) {
            int t = __shfl_up_sync(0xffffffffu, inc, d);
            if (lane >= d) inc += t;
        }
        if (lane == 31) wsum[wid] = inc;
        __syncthreads();
        if (wid == 0) {
            int w = wsum[lane];
            int wi = w;
            #pragma unroll
            for (int d = 1; d < 32; d <<= 1) {
                int t = __shfl_up_sync(0xffffffffu, wi, d);
                if (lane >= d) wi += t;
            }
            wsum[lane] = wi - w;
        }
        __syncthreads();
        int excl = s_carry + wsum[wid] + inc - t3;
        if (i < NQ) {
            int4 o = make_int4(excl, excl + t0, excl + t1, excl + t2);
            ((int4*)g_off)[i]  = o;
            ((int4*)g_fill)[i] = o;
            ((float4*)g_dinv)[i] = make_float4(rsqrtf((float)(v.x + 1)),
                                               rsqrtf((float)(v.y + 1)),
                                               rsqrtf((float)(v.z + 1)),
                                               rsqrtf((float)(v.w + 1)));
        }
        __syncthreads();
        if (tid == 1023) s_carry = excl + t3;
        __syncthreads();
    }
    if (tid == 0) g_off[NN] = s_carry;
}

__global__ void k_fill(const int* __restrict__ src,
                       const int* __restrict__ dst)
{
    int e = blockIdx.x * blockDim.x + threadIdx.x;
    if (e < NE) {
        int s = src[e];
        int d = dst[e];
        int p = atomicAdd(&g_fill[d], 1);
        g_edge[p] = make_int2(s, __float_as_int(g_dinv[s] * g_dinv[d]));
    }
}

// ---------------- GEMM: g_hA = Xin @ W  (Xin: [NN,96], W: [96,96]) ---------
// Xin = external x when Xext != nullptr (layer 0), else g_hB.
// BM=64, BN=96. 384 threads, each computes a 4x4 tile via f32x2 FMAs.
// Xs is stored k-major ([96][64]) so each thread's 4 a-operands are one LDS.128.
__global__ __launch_bounds__(384) void k_gemm(const float* __restrict__ Xext,
                                              const float* __restrict__ W)
{
    __shared__ float Ws[96 * 96];
    __shared__ float Xs[96 * 64];
    int tid = threadIdx.x;

    const float* X = Xext ? Xext : g_hB;

    const float4* W4  = (const float4*)W;
    float4*       Ws4 = (float4*)Ws;
    #pragma unroll
    for (int i = 0; i < 6; i++) Ws4[tid + i * 384] = W4[tid + i * 384];

    int row0 = blockIdx.x * 64;
    #pragma unroll
    for (int i = 0; i < 4; i++) {
        int idx = tid + i * 384;        // 0..1535 -> (m, q)
        int m = idx / 24, q = idx % 24;
        int row = row0 + m;
        float4 v = make_float4(0.f, 0.f, 0.f, 0.f);
        if (row < NN) v = ((const float4*)(X + (size_t)row * 96))[q];
        Xs[(q * 4 + 0) * 64 + m] = v.x;
        Xs[(q * 4 + 1) * 64 + m] = v.y;
        Xs[(q * 4 + 2) * 64 + m] = v.z;
        Xs[(q * 4 + 3) * 64 + m] = v.w;
    }
    __syncthreads();

    int tn = tid % 24;      // 4-col group
    int tm = tid / 24;      // 4-row group

    unsigned long long acc[4][2];
    unsigned long long z = pk2(0.f, 0.f);
    #pragma unroll
    for (int i = 0; i < 4; i++) { acc[i][0] = z; acc[i][1] = z; }

    #pragma unroll 4
    for (int k = 0; k < 96; k++) {
        float4 a4 = *(const float4*)&Xs[k * 64 + tm * 4];
        float4 b4 = *(const float4*)&Ws[k * 96 + tn * 4];
        unsigned long long b01 = pk2(b4.x, b4.y);
        unsigned long long b23 = pk2(b4.z, b4.w);
        unsigned long long aa;
        aa = pk2(a4.x, a4.x); ffma2(acc[0][0], aa, b01); ffma2(acc[0][1], aa, b23);
        aa = pk2(a4.y, a4.y); ffma2(acc[1][0], aa, b01); ffma2(acc[1][1], aa, b23);
        aa = pk2(a4.z, a4.z); ffma2(acc[2][0], aa, b01); ffma2(acc[2][1], aa, b23);
        aa = pk2(a4.w, a4.w); ffma2(acc[3][0], aa, b01); ffma2(acc[3][1], aa, b23);
    }

    #pragma unroll
    for (int i = 0; i < 4; i++) {
        int row = row0 + tm * 4 + i;
        if (row < NN) {
            float r0, r1, r2, r3;
            upk2(acc[i][0], r0, r1);
            upk2(acc[i][1], r2, r3);
            *(float4*)&g_hA[(size_t)row * 96 + tn * 4] = make_float4(r0, r1, r2, r3);
        }
    }
}

// ---------------- aggregation core (one warp per node) ---------------------
__device__ __forceinline__ void agg_node(int node, int lane,
                                         const float* __restrict__ bias,
                                         float& a0, float& a1, float& a2)
{
    const float* H = g_hA;

    float di = g_dinv[node];
    float wself = di * di;
    const float* hr = H + (size_t)node * 96;
    a0 = wself * hr[lane];
    a1 = wself * hr[lane + 32];
    a2 = wself * hr[lane + 64];

    int j  = g_off[node];
    int e1 = g_off[node + 1];
    for (; j + 1 < e1; j += 2) {
        int2 eA = g_edge[j];
        int2 eB = g_edge[j + 1];
        const float* ha = H + (size_t)eA.x * 96;
        const float* hb = H + (size_t)eB.x * 96;
        float wA = __int_as_float(eA.y);
        float wB = __int_as_float(eB.y);
        a0 += wA * ha[lane];
        a1 += wA * ha[lane + 32];
        a2 += wA * ha[lane + 64];
        a0 += wB * hb[lane];
        a1 += wB * hb[lane + 32];
        a2 += wB * hb[lane + 64];
    }
    if (j < e1) {
        int2 eA = g_edge[j];
        const float* ha = H + (size_t)eA.x * 96;
        float wA = __int_as_float(eA.y);
        a0 += wA * ha[lane];
        a1 += wA * ha[lane + 32];
        a2 += wA * ha[lane + 64];
    }
    a0 = fmaxf(a0 + bias[lane],      0.f);
    a1 = fmaxf(a1 + bias[lane + 32], 0.f);
    a2 = fmaxf(a2 + bias[lane + 64], 0.f);
}

// layers 0,1: g_hB = relu(A_hat @ g_hA + b)
__global__ __launch_bounds__(256) void k_agg(const float* __restrict__ bias)
{
    int node = blockIdx.x * 8 + threadIdx.y;
    if (node >= NN) return;
    int lane = threadIdx.x;

    float a0, a1, a2;
    agg_node(node, lane, bias, a0, a1, a2);

    size_t o = (size_t)node * 96 + lane;
    g_hB[o]      = a0;
    g_hB[o + 32] = a1;
    g_hB[o + 64] = a2;
}

// layer 2 + FC head fused: out = relu(A_hat @ g_hA + b2) @ Wfc + bfc
__global__ __launch_bounds__(256) void k_agg_fc(const float* __restrict__ bias,
                                                const float* __restrict__ Wfc,
                                                const float* __restrict__ bfc,
                                                float* __restrict__ Out)
{
    int node = blockIdx.x * 8 + threadIdx.y;
    if (node >= NN) return;
    int lane = threadIdx.x;

    float a0, a1, a2;
    agg_node(node, lane, bias, a0, a1, a2);

    const float4* W4 = (const float4*)Wfc;         // [96] rows of float4
    float4 w0 = W4[lane];
    float4 w1 = W4[lane + 32];
    float4 w2 = W4[lane + 64];

    float o0 = a0 * w0.x + a1 * w1.x + a2 * w2.x;
    float o1 = a0 * w0.y + a1 * w1.y + a2 * w2.y;
    float o2 = a0 * w0.z + a1 * w1.z + a2 * w2.z;
    float o3 = a0 * w0.w + a1 * w1.w + a2 * w2.w;

    #pragma unroll
    for (int d = 16; d > 0; d >>= 1) {
        o0 += __shfl_xor_sync(0xffffffffu, o0, d);
        o1 += __shfl_xor_sync(0xffffffffu, o1, d);
        o2 += __shfl_xor_sync(0xffffffffu, o2, d);
        o3 += __shfl_xor_sync(0xffffffffu, o3, d);
    }
    if (lane == 0) {
        const float4 bf = *(const float4*)bfc;
        *(float4*)&Out[(size_t)node * 4] =
            make_float4(o0 + bf.x, o1 + bf.y, o2 + bf.z, o3 + bf.w);
    }
}

// ---------------- launch ----------------------------------------------------
extern "C" void kernel_launch(void* const* d_in, const int* in_sizes, int n_in,
                              void* d_out, int out_size)
{
    const float* x    = (const float*)d_in[0];
    const int*   ei   = (const int*)d_in[1];     // int32, [2, NE]
    const float* W0   = (const float*)d_in[2];
    const float* b0   = (const float*)d_in[3];
    const float* W1   = (const float*)d_in[4];
    const float* b1   = (const float*)d_in[5];
    const float* W2   = (const float*)d_in[6];
    const float* b2   = (const float*)d_in[7];
    const float* Wfc  = (const float*)d_in[8];
    const float* bfc  = (const float*)d_in[9];
    float*       out  = (float*)d_out;

    const int* srcE = ei;
    const int* dstE = ei + NE;

    int gb_n = (NN + 255) / 256;
    int gb_e = (NE + 255) / 256;

    // graph preprocessing
    k_zero<<<gb_n, 256>>>();
    k_hist<<<gb_e, 256>>>(dstE);
    k_scan<<<1, 1024>>>();
    k_fill<<<gb_e, 256>>>(srcE, dstE);

    int gemm_blocks = (NN + 63) / 64;
    dim3 agg_block(32, 8);
    int agg_blocks = (NN + 7) / 8;

    // layer 0: gemm(x -> hA), agg(hA -> hB)
    k_gemm<<<gemm_blocks, 384>>>(x, W0);
    k_agg <<<agg_blocks, agg_block>>>(b0);
    // layer 1
    k_gemm<<<gemm_blocks, 384>>>(nullptr, W1);
    k_agg <<<agg_blocks, agg_block>>>(b1);
    // layer 2 + FC head fused
    k_gemm<<<gemm_blocks, 384>>>(nullptr, W2);
    k_agg_fc<<<agg_blocks, agg_block>>>(b2, Wfc, bfc, out);

    (void)in_sizes; (void)n_in; (void)out_size;
}

// round 5
// speedup vs baseline: 1.3044x; 1.0199x over previous
#include <cuda_runtime.h>

#define NN 50000
#define NE 800000
#define DD 96

// ---------------- scratch (device globals; no allocation allowed) ----------
__device__ __align__(16) int   g_cnt [NN];
__device__ __align__(16) int   g_off [NN + 4];
__device__ __align__(16) int   g_fill[NN];
__device__ __align__(16) float g_dinv[NN];
__device__ __align__(16) int2  g_edge[NE];      // .x = src, .y = bits(wn)
__device__ __align__(16) float g_hA[(size_t)NN * DD];
__device__ __align__(16) float g_hB[(size_t)NN * DD];

// ---------------- f32x2 helpers ---------------------------------------------
__device__ __forceinline__ unsigned long long pk2(float x, float y)
{
    unsigned long long r;
    asm("mov.b64 %0, {%1,%2};" : "=l"(r) : "f"(x), "f"(y));
    return r;
}
__device__ __forceinline__ void upk2(unsigned long long v, float& x, float& y)
{
    asm("mov.b64 {%0,%1}, %2;" : "=f"(x), "=f"(y) : "l"(v));
}
__device__ __forceinline__ void ffma2(unsigned long long& d,
                                      unsigned long long a,
                                      unsigned long long b)
{
    asm("fma.rn.f32x2 %0, %1, %2, %0;" : "+l"(d) : "l"(a), "l"(b));
}

// ---------------- graph preprocessing --------------------------------------
__global__ void k_zero()
{
    int i = blockIdx.x * blockDim.x + threadIdx.x;   // NN/4 = 12500 quads
    if (i * 4 < NN) ((int4*)g_cnt)[i] = make_int4(0, 0, 0, 0);
}

// 4 edges per thread: int4 index load, 4 independent atomic chains.
__global__ void k_hist(const int* __restrict__ dst)
{
    int i = (blockIdx.x * blockDim.x + threadIdx.x) * 4;
    if (i < NE) {
        int4 d = *(const int4*)&dst[i];
        atomicAdd(&g_cnt[d.x], 1);
        atomicAdd(&g_cnt[d.y], 1);
        atomicAdd(&g_cnt[d.z], 1);
        atomicAdd(&g_cnt[d.w], 1);
    }
}

// Single-block exclusive scan (4 elems/thread, int4): g_cnt -> g_off/g_fill,
// plus dinv = rsqrt(cnt+1).
__global__ void k_scan()
{
    __shared__ int wsum[32];
    __shared__ int s_carry;
    int tid = threadIdx.x, lane = tid & 31, wid = tid >> 5;
    if (tid == 0) s_carry = 0;
    __syncthreads();

    const int NQ = NN / 4;
    for (int base = 0; base < NQ; base += 1024) {
        int i = base + tid;
        int4 v = make_int4(0, 0, 0, 0);
        if (i < NQ) v = ((const int4*)g_cnt)[i];
        int t0 = v.x, t1 = t0 + v.y, t2 = t1 + v.z, t3 = t2 + v.w;

        int inc = t3;
        #pragma unroll
        for (int d = 1; d < 32; d <<= 1) {
            int t = __shfl_up_sync(0xffffffffu, inc, d);
            if (lane >= d) inc += t;
        }
        if (lane == 31) wsum[wid] = inc;
        __syncthreads();
        if (wid == 0) {
            int w = wsum[lane];
            int wi = w;
            #pragma unroll
            for (int d = 1; d < 32; d <<= 1) {
                int t = __shfl_up_sync(0xffffffffu, wi, d);
                if (lane >= d) wi += t;
            }
            wsum[lane] = wi - w;
        }
        __syncthreads();
        int excl = s_carry + wsum[wid] + inc - t3;
        if (i < NQ) {
            int4 o = make_int4(excl, excl + t0, excl + t1, excl + t2);
            ((int4*)g_off)[i]  = o;
            ((int4*)g_fill)[i] = o;
            ((float4*)g_dinv)[i] = make_float4(rsqrtf((float)(v.x + 1)),
                                               rsqrtf((float)(v.y + 1)),
                                               rsqrtf((float)(v.z + 1)),
                                               rsqrtf((float)(v.w + 1)));
        }
        __syncthreads();
        if (tid == 1023) s_carry = excl + t3;
        __syncthreads();
    }
    if (tid == 0) g_off[NN] = s_carry;
}

// 4 edges per thread: int4 loads of src+dst, 4 independent chains.
__global__ void k_fill(const int* __restrict__ src,
                       const int* __restrict__ dst)
{
    int i = (blockIdx.x * blockDim.x + threadIdx.x) * 4;
    if (i < NE) {
        int4 s = *(const int4*)&src[i];
        int4 d = *(const int4*)&dst[i];
        float ds0 = g_dinv[s.x], ds1 = g_dinv[s.y], ds2 = g_dinv[s.z], ds3 = g_dinv[s.w];
        float dd0 = g_dinv[d.x], dd1 = g_dinv[d.y], dd2 = g_dinv[d.z], dd3 = g_dinv[d.w];
        int p0 = atomicAdd(&g_fill[d.x], 1);
        int p1 = atomicAdd(&g_fill[d.y], 1);
        int p2 = atomicAdd(&g_fill[d.z], 1);
        int p3 = atomicAdd(&g_fill[d.w], 1);
        g_edge[p0] = make_int2(s.x, __float_as_int(ds0 * dd0));
        g_edge[p1] = make_int2(s.y, __float_as_int(ds1 * dd1));
        g_edge[p2] = make_int2(s.z, __float_as_int(ds2 * dd2));
        g_edge[p3] = make_int2(s.w, __float_as_int(ds3 * dd3));
    }
}

// ---------------- GEMM: g_hA = Xin @ W  (Xin: [NN,96], W: [96,96]) ---------
// Xin = external x when Xext != nullptr (layer 0), else g_hB.
// BM=64, BN=96. 384 threads, each computes a 4x4 tile via f32x2 FMAs.
// Xs is stored k-major ([96][64]) so each thread's 4 a-operands are one LDS.128.
__global__ __launch_bounds__(384) void k_gemm(const float* __restrict__ Xext,
                                              const float* __restrict__ W)
{
    __shared__ float Ws[96 * 96];
    __shared__ float Xs[96 * 64];
    int tid = threadIdx.x;

    const float* X = Xext ? Xext : g_hB;

    const float4* W4  = (const float4*)W;
    float4*       Ws4 = (float4*)Ws;
    #pragma unroll
    for (int i = 0; i < 6; i++) Ws4[tid + i * 384] = W4[tid + i * 384];

    int row0 = blockIdx.x * 64;
    #pragma unroll
    for (int i = 0; i < 4; i++) {
        int idx = tid + i * 384;        // 0..1535 -> (m, q)
        int m = idx / 24, q = idx % 24;
        int row = row0 + m;
        float4 v = make_float4(0.f, 0.f, 0.f, 0.f);
        if (row < NN) v = ((const float4*)(X + (size_t)row * 96))[q];
        Xs[(q * 4 + 0) * 64 + m] = v.x;
        Xs[(q * 4 + 1) * 64 + m] = v.y;
        Xs[(q * 4 + 2) * 64 + m] = v.z;
        Xs[(q * 4 + 3) * 64 + m] = v.w;
    }
    __syncthreads();

    int tn = tid % 24;      // 4-col group
    int tm = tid / 24;      // 4-row group

    unsigned long long acc[4][2];
    unsigned long long z = pk2(0.f, 0.f);
    #pragma unroll
    for (int i = 0; i < 4; i++) { acc[i][0] = z; acc[i][1] = z; }

    #pragma unroll 4
    for (int k = 0; k < 96; k++) {
        float4 a4 = *(const float4*)&Xs[k * 64 + tm * 4];
        float4 b4 = *(const float4*)&Ws[k * 96 + tn * 4];
        unsigned long long b01 = pk2(b4.x, b4.y);
        unsigned long long b23 = pk2(b4.z, b4.w);
        unsigned long long aa;
        aa = pk2(a4.x, a4.x); ffma2(acc[0][0], aa, b01); ffma2(acc[0][1], aa, b23);
        aa = pk2(a4.y, a4.y); ffma2(acc[1][0], aa, b01); ffma2(acc[1][1], aa, b23);
        aa = pk2(a4.z, a4.z); ffma2(acc[2][0], aa, b01); ffma2(acc[2][1], aa, b23);
        aa = pk2(a4.w, a4.w); ffma2(acc[3][0], aa, b01); ffma2(acc[3][1], aa, b23);
    }

    #pragma unroll
    for (int i = 0; i < 4; i++) {
        int row = row0 + tm * 4 + i;
        if (row < NN) {
            float r0, r1, r2, r3;
            upk2(acc[i][0], r0, r1);
            upk2(acc[i][1], r2, r3);
            *(float4*)&g_hA[(size_t)row * 96 + tn * 4] = make_float4(r0, r1, r2, r3);
        }
    }
}

// ---------------- aggregation core (one warp per node) ---------------------
// 4-edge unrolled: 12 independent H-row loads in flight per warp.
__device__ __forceinline__ void agg_node(int node, int lane,
                                         const float* __restrict__ bias,
                                         float& a0, float& a1, float& a2)
{
    const float* H = g_hA;

    float di = g_dinv[node];
    float wself = di * di;
    const float* hr = H + (size_t)node * 96;
    a0 = wself * hr[lane];
    a1 = wself * hr[lane + 32];
    a2 = wself * hr[lane + 64];

    int j  = g_off[node];
    int e1 = g_off[node + 1];

    for (; j + 3 < e1; j += 4) {
        int2 eA = g_edge[j];
        int2 eB = g_edge[j + 1];
        int2 eC = g_edge[j + 2];
        int2 eD = g_edge[j + 3];
        const float* ha = H + (size_t)eA.x * 96;
        const float* hb = H + (size_t)eB.x * 96;
        const float* hc = H + (size_t)eC.x * 96;
        const float* hd = H + (size_t)eD.x * 96;
        float wA = __int_as_float(eA.y);
        float wB = __int_as_float(eB.y);
        float wC = __int_as_float(eC.y);
        float wD = __int_as_float(eD.y);
        float vA0 = ha[lane], vA1 = ha[lane + 32], vA2 = ha[lane + 64];
        float vB0 = hb[lane], vB1 = hb[lane + 32], vB2 = hb[lane + 64];
        float vC0 = hc[lane], vC1 = hc[lane + 32], vC2 = hc[lane + 64];
        float vD0 = hd[lane], vD1 = hd[lane + 32], vD2 = hd[lane + 64];
        a0 += wA * vA0; a1 += wA * vA1; a2 += wA * vA2;
        a0 += wB * vB0; a1 += wB * vB1; a2 += wB * vB2;
        a0 += wC * vC0; a1 += wC * vC1; a2 += wC * vC2;
        a0 += wD * vD0; a1 += wD * vD1; a2 += wD * vD2;
    }
    for (; j < e1; j++) {
        int2 eA = g_edge[j];
        const float* ha = H + (size_t)eA.x * 96;
        float wA = __int_as_float(eA.y);
        a0 += wA * ha[lane];
        a1 += wA * ha[lane + 32];
        a2 += wA * ha[lane + 64];
    }
    a0 = fmaxf(a0 + bias[lane],      0.f);
    a1 = fmaxf(a1 + bias[lane + 32], 0.f);
    a2 = fmaxf(a2 + bias[lane + 64], 0.f);
}

// layers 0,1: g_hB = relu(A_hat @ g_hA + b)
__global__ __launch_bounds__(256) void k_agg(const float* __restrict__ bias)
{
    int node = blockIdx.x * 8 + threadIdx.y;
    if (node >= NN) return;
    int lane = threadIdx.x;

    float a0, a1, a2;
    agg_node(node, lane, bias, a0, a1, a2);

    size_t o = (size_t)node * 96 + lane;
    g_hB[o]      = a0;
    g_hB[o + 32] = a1;
    g_hB[o + 64] = a2;
}

// layer 2 + FC head fused: out = relu(A_hat @ g_hA + b2) @ Wfc + bfc
__global__ __launch_bounds__(256) void k_agg_fc(const float* __restrict__ bias,
                                                const float* __restrict__ Wfc,
                                                const float* __restrict__ bfc,
                                                float* __restrict__ Out)
{
    int node = blockIdx.x * 8 + threadIdx.y;
    if (node >= NN) return;
    int lane = threadIdx.x;

    float a0, a1, a2;
    agg_node(node, lane, bias, a0, a1, a2);

    const float4* W4 = (const float4*)Wfc;         // [96] rows of float4
    float4 w0 = W4[lane];
    float4 w1 = W4[lane + 32];
    float4 w2 = W4[lane + 64];

    float o0 = a0 * w0.x + a1 * w1.x + a2 * w2.x;
    float o1 = a0 * w0.y + a1 * w1.y + a2 * w2.y;
    float o2 = a0 * w0.z + a1 * w1.z + a2 * w2.z;
    float o3 = a0 * w0.w + a1 * w1.w + a2 * w2.w;

    #pragma unroll
    for (int d = 16; d > 0; d >>= 1) {
        o0 += __shfl_xor_sync(0xffffffffu, o0, d);
        o1 += __shfl_xor_sync(0xffffffffu, o1, d);
        o2 += __shfl_xor_sync(0xffffffffu, o2, d);
        o3 += __shfl_xor_sync(0xffffffffu, o3, d);
    }
    if (lane == 0) {
        const float4 bf = *(const float4*)bfc;
        *(float4*)&Out[(size_t)node * 4] =
            make_float4(o0 + bf.x, o1 + bf.y, o2 + bf.z, o3 + bf.w);
    }
}

// ---------------- launch ----------------------------------------------------
extern "C" void kernel_launch(void* const* d_in, const int* in_sizes, int n_in,
                              void* d_out, int out_size)
{
    const float* x    = (const float*)d_in[0];
    const int*   ei   = (const int*)d_in[1];     // int32, [2, NE]
    const float* W0   = (const float*)d_in[2];
    const float* b0   = (const float*)d_in[3];
    const float* W1   = (const float*)d_in[4];
    const float* b1   = (const float*)d_in[5];
    const float* W2   = (const float*)d_in[6];
    const float* b2   = (const float*)d_in[7];
    const float* Wfc  = (const float*)d_in[8];
    const float* bfc  = (const float*)d_in[9];
    float*       out  = (float*)d_out;

    const int* srcE = ei;
    const int* dstE = ei + NE;

    int gb_zero = (NN / 4 + 255) / 256;
    int gb_e4   = (NE / 4 + 255) / 256;

    // graph preprocessing
    k_zero<<<gb_zero, 256>>>();
    k_hist<<<gb_e4, 256>>>(dstE);
    k_scan<<<1, 1024>>>();
    k_fill<<<gb_e4, 256>>>(srcE, dstE);

    int gemm_blocks = (NN + 63) / 64;
    dim3 agg_block(32, 8);
    int agg_blocks = (NN + 7) / 8;

    // layer 0: gemm(x -> hA), agg(hA -> hB)
    k_gemm<<<gemm_blocks, 384>>>(x, W0);
    k_agg <<<agg_blocks, agg_block>>>(b0);
    // layer 1
    k_gemm<<<gemm_blocks, 384>>>(nullptr, W1);
    k_agg <<<agg_blocks, agg_block>>>(b1);
    // layer 2 + FC head fused
    k_gemm<<<gemm_blocks, 384>>>(nullptr, W2);
    k_agg_fc<<<agg_blocks, agg_block>>>(b2, Wfc, bfc, out);

    (void)in_sizes; (void)n_in; (void)out_size;
}